// round 12
// baseline (speedup 1.0000x reference)
#include <cuda_runtime.h>
#include <cstdint>

// EmbeddingDropout: out[r, :] = weight[x[r], :] * rowmask(x[r])
// rowmask: bit-exact jax.random.bernoulli(jax.random.key(42), 0.9, (50257,1))
// under the partitionable threefry path (JAX >= 0.4.30 default):
//   (o0,o1) = threefry2x32(key=(0,42), (hi32(v)=0, lo32(v)=v)); bits = o0^o1
//   u = bitcast((bits>>9)|0x3f800000) - 1.0f;  keep = u < 0.9f; scale = keep/0.9
// x indices arrive as int32 (JAX x64-disabled demotes jnp.int64 -> int32).
//
// Cache-policy steering:
//   weight loads:  ld.global.nc.L2::evict_last.v8.b32 (256-bit LDG, as sm_103
//                  requires for the evict_last hint) -> pin gather set in L2
//   output stores: st.global.cs (evict-first) -> streaming writes skip L2

#define TF_ROUND(r) { x0 += x1; x1 = (x1 << (r)) | (x1 >> (32 - (r))); x1 ^= x0; }

__device__ __forceinline__ float row_scale(uint32_t v)
{
    const uint32_t k0 = 0u;
    const uint32_t k1 = 42u;
    const uint32_t k2 = 0u ^ 42u ^ 0x1BD11BDAu;

    uint32_t x0 = 0u;   // hi32 of uint64 counter
    uint32_t x1 = v;    // lo32

    x0 += k0; x1 += k1;
    TF_ROUND(13) TF_ROUND(15) TF_ROUND(26) TF_ROUND(6)
    x0 += k1; x1 += k2 + 1u;
    TF_ROUND(17) TF_ROUND(29) TF_ROUND(16) TF_ROUND(24)
    x0 += k2; x1 += k0 + 2u;
    TF_ROUND(13) TF_ROUND(15) TF_ROUND(26) TF_ROUND(6)
    x0 += k0; x1 += k1 + 3u;
    TF_ROUND(17) TF_ROUND(29) TF_ROUND(16) TF_ROUND(24)
    x0 += k1; x1 += k2 + 4u;
    TF_ROUND(13) TF_ROUND(15) TF_ROUND(26) TF_ROUND(6)
    x0 += k2; x1 += k0 + 5u;

    uint32_t bits = x0 ^ x1;

    float u = __uint_as_float((bits >> 9) | 0x3f800000u) - 1.0f;
    return (u < 0.9f) ? (1.0f / 0.9f) : 0.0f;
}

// 256-bit evict-last load: 8 x b32 from a 32B-aligned address.
__device__ __forceinline__ void ldg256_evict_last(const float* p,
                                                  float4& a, float4& b)
{
    uint32_t r0, r1, r2, r3, r4, r5, r6, r7;
    asm volatile(
        "ld.global.nc.L2::evict_last.v8.b32 {%0,%1,%2,%3,%4,%5,%6,%7}, [%8];"
        : "=r"(r0), "=r"(r1), "=r"(r2), "=r"(r3),
          "=r"(r4), "=r"(r5), "=r"(r6), "=r"(r7)
        : "l"(p));
    a.x = __uint_as_float(r0); a.y = __uint_as_float(r1);
    a.z = __uint_as_float(r2); a.w = __uint_as_float(r3);
    b.x = __uint_as_float(r4); b.y = __uint_as_float(r5);
    b.z = __uint_as_float(r6); b.w = __uint_as_float(r7);
}

// 4 rows per CTA (256 threads): 64 threads per row, 2 x 32B loads per thread
// (64B/thread). Same proven shape as R4, with 256-bit loads + cache steering.
__global__ void __launch_bounds__(256, 8)
embedding_dropout_kernel(const int* __restrict__ x,
                         const float* __restrict__ weight,
                         float* __restrict__ out)
{
    const int sub = threadIdx.x >> 6;          // 0..3: row within CTA
    const int t   = threadIdx.x & 63;          // 0..63: lane within row
    const int row = (blockIdx.x << 2) + sub;

    int idx = x[row];
    idx = (idx < 0) ? 0 : ((idx > 50256) ? 50256 : idx);

    const float s = row_scale((uint32_t)idx);

    // Lane t covers floats [t*8, t*8+8) and [512 + t*8, 512 + t*8+8).
    const float* __restrict__ src = weight + (long long)idx * 1024ll + t * 8;
    float4* __restrict__ dst =
        reinterpret_cast<float4*>(out + (long long)row * 1024ll) + t * 2;

    // 2 independent 256-bit evict-last loads in flight before any store.
    float4 a0, a1, b0, b1;
    ldg256_evict_last(src,       a0, a1);
    ldg256_evict_last(src + 512, b0, b1);

    a0.x *= s; a0.y *= s; a0.z *= s; a0.w *= s;
    a1.x *= s; a1.y *= s; a1.z *= s; a1.w *= s;
    b0.x *= s; b0.y *= s; b0.z *= s; b0.w *= s;
    b1.x *= s; b1.y *= s; b1.z *= s; b1.w *= s;

    // Streaming (evict-first) stores: output is never re-read.
    __stcs(dst,       a0);
    __stcs(dst + 1,   a1);
    __stcs(dst + 128, b0);   // 512 floats = 128 float4s later
    __stcs(dst + 129, b1);
}

extern "C" void kernel_launch(void* const* d_in, const int* in_sizes, int n_in,
                              void* d_out, int out_size)
{
    // Robust to input ordering: x has 16,384 elements, weight has 51,463,168.
    int xi = 0, wi = 1;
    if (n_in >= 2 && in_sizes[0] > in_sizes[1]) { xi = 1; wi = 0; }

    const int* x = (const int*)d_in[xi];          // int32 [8,2048]
    const float* weight = (const float*)d_in[wi]; // f32 [50257,1024]
    float* out = (float*)d_out;                   // f32 [8,2048,1024]

    const int n_rows = in_sizes[xi];              // 16384 (divisible by 4)
    embedding_dropout_kernel<<<n_rows / 4, 256>>>(x, weight, out);
}

// round 13
// speedup vs baseline: 1.3795x; 1.3795x over previous
#include <cuda_runtime.h>
#include <cstdint>

// EmbeddingDropout: out[r, :] = weight[x[r], :] * rowmask(x[r])
// rowmask: bit-exact jax.random.bernoulli(jax.random.key(42), 0.9, (50257,1))
// under the partitionable threefry path (JAX >= 0.4.30 default):
//   (o0,o1) = threefry2x32(key=(0,42), (hi32(v)=0, lo32(v)=v)); bits = o0^o1
//   u = bitcast((bits>>9)|0x3f800000) - 1.0f;  keep = u < 0.9f; scale = keep/0.9
// x indices arrive as int32 (JAX x64-disabled demotes jnp.int64 -> int32).
//
// R12 change (single variable vs the 17.9us R9 kernel): output stores are
// st.global.cs (evict-first streaming) so the 64MB write stream stops
// evicting the 56MB gather set from L2. Loads unchanged (plain LDG.128.nc).

#define TF_ROUND(r) { x0 += x1; x1 = (x1 << (r)) | (x1 >> (32 - (r))); x1 ^= x0; }

__device__ __forceinline__ float row_scale(uint32_t v)
{
    const uint32_t k0 = 0u;
    const uint32_t k1 = 42u;
    const uint32_t k2 = 0u ^ 42u ^ 0x1BD11BDAu;

    uint32_t x0 = 0u;   // hi32 of uint64 counter
    uint32_t x1 = v;    // lo32

    x0 += k0; x1 += k1;
    TF_ROUND(13) TF_ROUND(15) TF_ROUND(26) TF_ROUND(6)
    x0 += k1; x1 += k2 + 1u;
    TF_ROUND(17) TF_ROUND(29) TF_ROUND(16) TF_ROUND(24)
    x0 += k2; x1 += k0 + 2u;
    TF_ROUND(13) TF_ROUND(15) TF_ROUND(26) TF_ROUND(6)
    x0 += k0; x1 += k1 + 3u;
    TF_ROUND(17) TF_ROUND(29) TF_ROUND(16) TF_ROUND(24)
    x0 += k1; x1 += k2 + 4u;
    TF_ROUND(13) TF_ROUND(15) TF_ROUND(26) TF_ROUND(6)
    x0 += k2; x1 += k0 + 5u;

    uint32_t bits = x0 ^ x1;

    float u = __uint_as_float((bits >> 9) | 0x3f800000u) - 1.0f;
    return (u < 0.9f) ? (1.0f / 0.9f) : 0.0f;
}

// 4 rows per CTA (256 threads): 64 threads per row, 4 named float4s per
// thread (the proven shape: genuine MLP=4 in SASS at ~26 regs).
__global__ void __launch_bounds__(256, 8)
embedding_dropout_kernel(const int* __restrict__ x,
                         const float* __restrict__ weight,
                         float* __restrict__ out)
{
    const int sub = threadIdx.x >> 6;          // 0..3: row within CTA
    const int t   = threadIdx.x & 63;          // 0..63: lane within row
    const int row = (blockIdx.x << 2) + sub;

    int idx = x[row];
    idx = (idx < 0) ? 0 : ((idx > 50256) ? 50256 : idx);

    const float s = row_scale((uint32_t)idx);

    const float4* __restrict__ src =
        reinterpret_cast<const float4*>(weight + (long long)idx * 1024ll) + t;
    float4* __restrict__ dst =
        reinterpret_cast<float4*>(out + (long long)row * 1024ll) + t;

    // 4 independent loads in flight before any store.
    float4 v0 = __ldg(src);
    float4 v1 = __ldg(src + 64);
    float4 v2 = __ldg(src + 128);
    float4 v3 = __ldg(src + 192);

    v0.x *= s; v0.y *= s; v0.z *= s; v0.w *= s;
    v1.x *= s; v1.y *= s; v1.z *= s; v1.w *= s;
    v2.x *= s; v2.y *= s; v2.z *= s; v2.w *= s;
    v3.x *= s; v3.y *= s; v3.z *= s; v3.w *= s;

    // Streaming (evict-first) stores: output is never re-read; keep it from
    // evicting the weight gather set out of L2.
    __stcs(dst,       v0);
    __stcs(dst + 64,  v1);
    __stcs(dst + 128, v2);
    __stcs(dst + 192, v3);
}

extern "C" void kernel_launch(void* const* d_in, const int* in_sizes, int n_in,
                              void* d_out, int out_size)
{
    // Robust to input ordering: x has 16,384 elements, weight has 51,463,168.
    int xi = 0, wi = 1;
    if (n_in >= 2 && in_sizes[0] > in_sizes[1]) { xi = 1; wi = 0; }

    const int* x = (const int*)d_in[xi];          // int32 [8,2048]
    const float* weight = (const float*)d_in[wi]; // f32 [50257,1024]
    float* out = (float*)d_out;                   // f32 [8,2048,1024]

    const int n_rows = in_sizes[xi];              // 16384 (divisible by 4)
    embedding_dropout_kernel<<<n_rows / 4, 256>>>(x, weight, out);
}